// round 1
// baseline (speedup 1.0000x reference)
#include <cuda_runtime.h>
#include <cuda_bf16.h>

// Problem constants (fixed shapes per reference setup_inputs)
#define T_TOK 2048      // bs * slen = 2 * 1024
#define DIM   1024
#define HID   2048
#define NE    8         // experts
// top_k = 2 (hardcoded)

// ---------------- scratch (device globals; no allocations allowed) ----------
__device__ int   g_count[NE];
__device__ int   g_tok[NE * T_TOK];
__device__ float g_score[NE * T_TOK];
__device__ float g_H[(size_t)NE * T_TOK * HID];   // 128 MiB hidden scratch

__device__ __forceinline__ float silu_f(float v) {
    return v / (1.0f + __expf(-v));
}

// ---------------- kernel 0: zero counts + output ----------------------------
__global__ void zero_kernel(float* __restrict__ out, int n4) {
    int idx = blockIdx.x * blockDim.x + threadIdx.x;
    if (idx < n4) {
        ((float4*)out)[idx] = make_float4(0.f, 0.f, 0.f, 0.f);
    }
    if (blockIdx.x == 0 && threadIdx.x < NE) g_count[threadIdx.x] = 0;
}

// ---------------- kernel 1: router (warp per token) --------------------------
__global__ void router_kernel(const float* __restrict__ x,
                              const float* __restrict__ rw) {
    int warp = threadIdx.x >> 5;
    int lane = threadIdx.x & 31;
    int tok = blockIdx.x * 4 + warp;
    if (tok >= T_TOK) return;

    const float* xr = x + (size_t)tok * DIM;
    float xv[32];
#pragma unroll
    for (int j = 0; j < 32; j++) xv[j] = xr[lane + 32 * j];

    float logit[NE];
#pragma unroll
    for (int e = 0; e < NE; e++) {
        float p = 0.f;
#pragma unroll
        for (int j = 0; j < 32; j++) p += xv[j] * rw[(lane + 32 * j) * NE + e];
#pragma unroll
        for (int o = 16; o > 0; o >>= 1) p += __shfl_xor_sync(0xffffffffu, p, o);
        logit[e] = p;
    }

    if (lane == 0) {
        float mx = logit[0];
#pragma unroll
        for (int e = 1; e < NE; e++) mx = fmaxf(mx, logit[e]);
        float pr[NE];
        float sum = 0.f;
#pragma unroll
        for (int e = 0; e < NE; e++) { pr[e] = __expf(logit[e] - mx); sum += pr[e]; }
        float inv = 1.f / sum;
#pragma unroll
        for (int e = 0; e < NE; e++) pr[e] *= inv;

        // top-1 (ties -> lowest index, matching jax top_k)
        int i1 = 0;
#pragma unroll
        for (int e = 1; e < NE; e++) if (pr[e] > pr[i1]) i1 = e;
        // top-2
        int i2 = -1;
#pragma unroll
        for (int e = 0; e < NE; e++) {
            if (e == i1) continue;
            if (i2 < 0 || pr[e] > pr[i2]) i2 = e;
        }
        int s1 = atomicAdd(&g_count[i1], 1);
        g_tok[i1 * T_TOK + s1] = tok;
        g_score[i1 * T_TOK + s1] = pr[i1];
        int s2 = atomicAdd(&g_count[i2], 1);
        g_tok[i2 * T_TOK + s2] = tok;
        g_score[i2 * T_TOK + s2] = pr[i2];
    }
}

// ---------------- kernel 2: H = silu(X@W1) * (X@W3), per expert -------------
// Block tile 128(M) x 64(N) x 8(K), 256 threads, per-thread 8x4 micro-tile,
// two accumulators (w1 and w3 paths share the gathered A tile).
__global__ __launch_bounds__(256) void gemm_h_kernel(const float* __restrict__ x,
                                                     const float* __restrict__ w1,
                                                     const float* __restrict__ w3) {
    int e = blockIdx.z;
    int cnt = g_count[e];
    int row0 = blockIdx.y * 128;
    if (row0 >= cnt) return;
    int n0 = blockIdx.x * 64;

    __shared__ float As[8][128];
    __shared__ float B1[8][64];
    __shared__ float B3[8][64];

    int tid = threadIdx.x;
    int tx = tid & 15;         // N: n0 + tx*4 + j
    int ty = tid >> 4;         // M: ty*8 + i

    // A-load mapping: each thread loads one float4 of X (gathered, scaled)
    int am = tid >> 1;               // 0..127
    int ak = (tid & 1) * 4;          // 0 or 4
    int arow = row0 + am;
    int atok = 0;
    float ascale = 0.f;
    if (arow < cnt) { atok = g_tok[e * T_TOK + arow]; ascale = g_score[e * T_TOK + arow]; }
    const float* aptr = x + (size_t)atok * DIM + ak;

    // B-load mapping: half the threads load W1, half W3 (one float4 each)
    int bsel = tid >> 7;             // 0 -> W1, 1 -> W3
    int br = tid & 127;
    int bk = br >> 4;                // 0..7
    int bn = (br & 15) * 4;
    const float* wsrc = bsel ? w3 : w1;
    const float* bptr = wsrc + ((size_t)e * DIM + bk) * HID + n0 + bn;

    float acc1[8][4], acc3[8][4];
#pragma unroll
    for (int i = 0; i < 8; i++)
#pragma unroll
        for (int j = 0; j < 4; j++) { acc1[i][j] = 0.f; acc3[i][j] = 0.f; }

    for (int k0 = 0; k0 < DIM; k0 += 8) {
        float4 av = make_float4(0.f, 0.f, 0.f, 0.f);
        if (arow < cnt) av = *(const float4*)(aptr + k0);
        float4 bv = *(const float4*)(bptr + (size_t)k0 * HID);

        __syncthreads();
        As[ak + 0][am] = av.x * ascale;
        As[ak + 1][am] = av.y * ascale;
        As[ak + 2][am] = av.z * ascale;
        As[ak + 3][am] = av.w * ascale;
        if (bsel == 0) *(float4*)&B1[bk][bn] = bv;
        else           *(float4*)&B3[bk][bn] = bv;
        __syncthreads();

#pragma unroll
        for (int kk = 0; kk < 8; kk++) {
            float4 a0 = *(const float4*)&As[kk][ty * 8 + 0];
            float4 a1 = *(const float4*)&As[kk][ty * 8 + 4];
            float4 b1 = *(const float4*)&B1[kk][tx * 4];
            float4 b3 = *(const float4*)&B3[kk][tx * 4];
            float a[8] = {a0.x, a0.y, a0.z, a0.w, a1.x, a1.y, a1.z, a1.w};
#pragma unroll
            for (int i = 0; i < 8; i++) {
                acc1[i][0] += a[i] * b1.x; acc1[i][1] += a[i] * b1.y;
                acc1[i][2] += a[i] * b1.z; acc1[i][3] += a[i] * b1.w;
                acc3[i][0] += a[i] * b3.x; acc3[i][1] += a[i] * b3.y;
                acc3[i][2] += a[i] * b3.z; acc3[i][3] += a[i] * b3.w;
            }
        }
    }

#pragma unroll
    for (int i = 0; i < 8; i++) {
        int row = row0 + ty * 8 + i;
        if (row < cnt) {
            float4 o;
            o.x = silu_f(acc1[i][0]) * acc3[i][0];
            o.y = silu_f(acc1[i][1]) * acc3[i][1];
            o.z = silu_f(acc1[i][2]) * acc3[i][2];
            o.w = silu_f(acc1[i][3]) * acc3[i][3];
            *(float4*)&g_H[((size_t)e * T_TOK + row) * HID + n0 + tx * 4] = o;
        }
    }
}

// ---------------- kernel 3: Y = H @ W2, scatter-add into out -----------------
__global__ __launch_bounds__(256) void gemm_o_kernel(const float* __restrict__ w2,
                                                     float* __restrict__ out) {
    int e = blockIdx.z;
    int cnt = g_count[e];
    int row0 = blockIdx.y * 128;
    if (row0 >= cnt) return;
    int n0 = blockIdx.x * 64;

    __shared__ float As[8][128];
    __shared__ float Bs[8][64];

    int tid = threadIdx.x;
    int tx = tid & 15;
    int ty = tid >> 4;

    int am = tid >> 1;
    int ak = (tid & 1) * 4;
    int arow = row0 + am;
    const float* aptr = g_H + ((size_t)e * T_TOK + (arow < cnt ? arow : 0)) * HID + ak;
    bool avalid = (arow < cnt);

    int bk = (tid & 127) >> 4;
    int bn = ((tid & 127) & 15) * 4;
    const float* bptr = w2 + ((size_t)e * HID + bk) * DIM + n0 + bn;
    bool bload = (tid < 128);

    float acc[8][4];
#pragma unroll
    for (int i = 0; i < 8; i++)
#pragma unroll
        for (int j = 0; j < 4; j++) acc[i][j] = 0.f;

    for (int k0 = 0; k0 < HID; k0 += 8) {
        float4 av = make_float4(0.f, 0.f, 0.f, 0.f);
        if (avalid) av = *(const float4*)(aptr + k0);
        float4 bv = make_float4(0.f, 0.f, 0.f, 0.f);
        if (bload) bv = *(const float4*)(bptr + (size_t)k0 * DIM);

        __syncthreads();
        As[ak + 0][am] = av.x;
        As[ak + 1][am] = av.y;
        As[ak + 2][am] = av.z;
        As[ak + 3][am] = av.w;
        if (bload) *(float4*)&Bs[bk][bn] = bv;
        __syncthreads();

#pragma unroll
        for (int kk = 0; kk < 8; kk++) {
            float4 a0 = *(const float4*)&As[kk][ty * 8 + 0];
            float4 a1 = *(const float4*)&As[kk][ty * 8 + 4];
            float4 b = *(const float4*)&Bs[kk][tx * 4];
            float a[8] = {a0.x, a0.y, a0.z, a0.w, a1.x, a1.y, a1.z, a1.w};
#pragma unroll
            for (int i = 0; i < 8; i++) {
                acc[i][0] += a[i] * b.x; acc[i][1] += a[i] * b.y;
                acc[i][2] += a[i] * b.z; acc[i][3] += a[i] * b.w;
            }
        }
    }

#pragma unroll
    for (int i = 0; i < 8; i++) {
        int row = row0 + ty * 8 + i;
        if (row < cnt) {
            int tok = g_tok[e * T_TOK + row];
            float* op = out + (size_t)tok * DIM + n0 + tx * 4;
            atomicAdd(op + 0, acc[i][0]);
            atomicAdd(op + 1, acc[i][1]);
            atomicAdd(op + 2, acc[i][2]);
            atomicAdd(op + 3, acc[i][3]);
        }
    }
}

// ---------------- launch ------------------------------------------------------
extern "C" void kernel_launch(void* const* d_in, const int* in_sizes, int n_in,
                              void* d_out, int out_size) {
    const float* x  = (const float*)d_in[0];   // [2,1024,1024]
    const float* rw = (const float*)d_in[1];   // [1024,8]
    const float* w1 = (const float*)d_in[2];   // [8,1024,2048]
    const float* w2 = (const float*)d_in[3];   // [8,2048,1024]
    const float* w3 = (const float*)d_in[4];   // [8,1024,2048]
    float* out = (float*)d_out;                // [2,1024,1024]

    int n4 = (T_TOK * DIM) / 4;
    zero_kernel<<<(n4 + 255) / 256, 256>>>(out, n4);
    router_kernel<<<T_TOK / 4, 128>>>(x, rw);

    dim3 gh(HID / 64, T_TOK / 128, NE);   // (32, 16, 8)
    gemm_h_kernel<<<gh, 256>>>(x, w1, w3);

    dim3 go(DIM / 64, T_TOK / 128, NE);   // (16, 16, 8)
    gemm_o_kernel<<<go, 256>>>(w2, out);
}

// round 3
// speedup vs baseline: 1.9108x; 1.9108x over previous
#include <cuda_runtime.h>
#include <cuda_bf16.h>

#define T_TOK 2048
#define DIM   1024
#define HID   2048
#define NE    8

// ---------------- scratch ----------------------------------------------------
__device__ int   g_count[NE];
__device__ int   g_tok[NE * T_TOK];
__device__ float g_score[NE * T_TOK];
__device__ float g_H[(size_t)NE * T_TOK * HID];   // hidden activations

__device__ __forceinline__ float silu_f(float v) {
    return v / (1.0f + __expf(-v));
}

__device__ __forceinline__ unsigned f2tf32(float f) {
    unsigned r;
    asm("cvt.rna.tf32.f32 %0, %1;" : "=r"(r) : "f"(f));
    return r;
}

__device__ __forceinline__ void mma_tf32(float c[4], const unsigned a[4],
                                         unsigned b0, unsigned b1) {
    asm volatile(
        "mma.sync.aligned.m16n8k8.row.col.f32.tf32.tf32.f32 "
        "{%0,%1,%2,%3}, {%4,%5,%6,%7}, {%8,%9}, {%0,%1,%2,%3};"
        : "+f"(c[0]), "+f"(c[1]), "+f"(c[2]), "+f"(c[3])
        : "r"(a[0]), "r"(a[1]), "r"(a[2]), "r"(a[3]), "r"(b0), "r"(b1));
}

// ---------------- kernel 0: zero counts + output ----------------------------
__global__ void zero_kernel(float* __restrict__ out, int n4) {
    int idx = blockIdx.x * blockDim.x + threadIdx.x;
    if (idx < n4) ((float4*)out)[idx] = make_float4(0.f, 0.f, 0.f, 0.f);
    if (blockIdx.x == 0 && threadIdx.x < NE) g_count[threadIdx.x] = 0;
}

// ---------------- kernel 1: router -------------------------------------------
__global__ void router_kernel(const float* __restrict__ x,
                              const float* __restrict__ rw) {
    int warp = threadIdx.x >> 5;
    int lane = threadIdx.x & 31;
    int tok = blockIdx.x * 4 + warp;
    if (tok >= T_TOK) return;

    const float* xr = x + (size_t)tok * DIM;
    float xv[32];
#pragma unroll
    for (int j = 0; j < 32; j++) xv[j] = xr[lane + 32 * j];

    float logit[NE];
#pragma unroll
    for (int e = 0; e < NE; e++) {
        float p = 0.f;
#pragma unroll
        for (int j = 0; j < 32; j++) p += xv[j] * rw[(lane + 32 * j) * NE + e];
#pragma unroll
        for (int o = 16; o > 0; o >>= 1) p += __shfl_xor_sync(0xffffffffu, p, o);
        logit[e] = p;
    }

    if (lane == 0) {
        float mx = logit[0];
#pragma unroll
        for (int e = 1; e < NE; e++) mx = fmaxf(mx, logit[e]);
        float pr[NE]; float sum = 0.f;
#pragma unroll
        for (int e = 0; e < NE; e++) { pr[e] = __expf(logit[e] - mx); sum += pr[e]; }
        float inv = 1.f / sum;
#pragma unroll
        for (int e = 0; e < NE; e++) pr[e] *= inv;

        int i1 = 0;
#pragma unroll
        for (int e = 1; e < NE; e++) if (pr[e] > pr[i1]) i1 = e;
        int i2 = -1;
#pragma unroll
        for (int e = 0; e < NE; e++) {
            if (e == i1) continue;
            if (i2 < 0 || pr[e] > pr[i2]) i2 = e;
        }
        int s1 = atomicAdd(&g_count[i1], 1);
        g_tok[i1 * T_TOK + s1] = tok;  g_score[i1 * T_TOK + s1] = pr[i1];
        int s2 = atomicAdd(&g_count[i2], 1);
        g_tok[i2 * T_TOK + s2] = tok;  g_score[i2 * T_TOK + s2] = pr[i2];
    }
}

// ---------------- kernel 2: H = silu(X@W1) * (X@W3), TF32 mma ----------------
// Block: 128(M) x 64(N-cols of both W1 and W3) x K-tile 32. 8 warps = 4M x 2N.
// Each warp: 32m x 32n for BOTH W1 and W3 paths.
__global__ __launch_bounds__(256) void gemm_h_kernel(const float* __restrict__ x,
                                                     const float* __restrict__ w1,
                                                     const float* __restrict__ w3) {
    int e = blockIdx.z;
    int cnt = g_count[e];
    int row0 = blockIdx.y * 128;
    if (row0 >= cnt) return;
    int n0 = blockIdx.x * 64;

    __shared__ unsigned As[32][136];   // [k][m], ldm=136 -> conflict-free frags
    __shared__ unsigned B1s[32][72];   // [k][n], ldb=72
    __shared__ unsigned B3s[32][72];
    __shared__ int   s_tok[128];
    __shared__ float s_sc[128];

    int tid = threadIdx.x;
    int warp = tid >> 5, lane = tid & 31;
    int q = lane & 3, g = lane >> 2;
    int wm = warp >> 1, wn = warp & 1;
    int mb = wm * 32;          // warp m base inside block
    int nb = wn * 32;          // warp n base inside 64-col B tile

    if (tid < 128) {
        int r = row0 + tid;
        if (r < cnt) { s_tok[tid] = g_tok[e * T_TOK + r]; s_sc[tid] = g_score[e * T_TOK + r]; }
        else         { s_tok[tid] = 0; s_sc[tid] = 0.f; }
    }
    __syncthreads();

    float acc1[2][4][4], acc3[2][4][4];
#pragma unroll
    for (int a = 0; a < 2; a++)
#pragma unroll
        for (int b = 0; b < 4; b++)
#pragma unroll
            for (int c = 0; c < 4; c++) { acc1[a][b][c] = 0.f; acc3[a][b][c] = 0.f; }

    const float* w1b = w1 + (size_t)e * DIM * HID + n0;
    const float* w3b = w3 + (size_t)e * DIM * HID + n0;

    for (int kt = 0; kt < DIM; kt += 32) {
        // load A: 128 rows x 32 k = 1024 float4
#pragma unroll
        for (int i = tid; i < 1024; i += 256) {
            int m = i >> 3, k4 = (i & 7) << 2;
            float4 v = make_float4(0.f, 0.f, 0.f, 0.f);
            float s = s_sc[m];
            if (row0 + m < cnt)
                v = *(const float4*)(x + (size_t)s_tok[m] * DIM + kt + k4);
            As[k4 + 0][m] = f2tf32(v.x * s);
            As[k4 + 1][m] = f2tf32(v.y * s);
            As[k4 + 2][m] = f2tf32(v.z * s);
            As[k4 + 3][m] = f2tf32(v.w * s);
        }
        // load B1/B3: 32 rows x 64 cols = 512 float4 each
#pragma unroll
        for (int i = tid; i < 512; i += 256) {
            int k = i >> 4, c4 = (i & 15) << 2;
            float4 v1 = *(const float4*)(w1b + (size_t)(kt + k) * HID + c4);
            float4 v3 = *(const float4*)(w3b + (size_t)(kt + k) * HID + c4);
            B1s[k][c4 + 0] = f2tf32(v1.x); B1s[k][c4 + 1] = f2tf32(v1.y);
            B1s[k][c4 + 2] = f2tf32(v1.z); B1s[k][c4 + 3] = f2tf32(v1.w);
            B3s[k][c4 + 0] = f2tf32(v3.x); B3s[k][c4 + 1] = f2tf32(v3.y);
            B3s[k][c4 + 2] = f2tf32(v3.z); B3s[k][c4 + 3] = f2tf32(v3.w);
        }
        __syncthreads();

#pragma unroll
        for (int ks = 0; ks < 4; ks++) {
            int k8 = ks * 8;
            unsigned a[2][4];
#pragma unroll
            for (int mt = 0; mt < 2; mt++) {
                int m = mb + mt * 16 + g;
                a[mt][0] = As[k8 + q][m];
                a[mt][1] = As[k8 + q][m + 8];
                a[mt][2] = As[k8 + q + 4][m];
                a[mt][3] = As[k8 + q + 4][m + 8];
            }
#pragma unroll
            for (int nt = 0; nt < 4; nt++) {
                int n = nb + nt * 8 + g;
                unsigned b0 = B1s[k8 + q][n];
                unsigned b1 = B1s[k8 + q + 4][n];
                mma_tf32(acc1[0][nt], a[0], b0, b1);
                mma_tf32(acc1[1][nt], a[1], b0, b1);
                unsigned c0 = B3s[k8 + q][n];
                unsigned c1 = B3s[k8 + q + 4][n];
                mma_tf32(acc3[0][nt], a[0], c0, c1);
                mma_tf32(acc3[1][nt], a[1], c0, c1);
            }
        }
        __syncthreads();
    }

    // epilogue: h = silu(c1) * c3 -> g_H
#pragma unroll
    for (int mt = 0; mt < 2; mt++) {
#pragma unroll
        for (int nt = 0; nt < 4; nt++) {
            int col = n0 + nb + nt * 8 + 2 * q;
            int r0 = row0 + mb + mt * 16 + g;
            int r1 = r0 + 8;
            if (r0 < cnt) {
                float2 o;
                o.x = silu_f(acc1[mt][nt][0]) * acc3[mt][nt][0];
                o.y = silu_f(acc1[mt][nt][1]) * acc3[mt][nt][1];
                *(float2*)&g_H[((size_t)e * T_TOK + r0) * HID + col] = o;
            }
            if (r1 < cnt) {
                float2 o;
                o.x = silu_f(acc1[mt][nt][2]) * acc3[mt][nt][2];
                o.y = silu_f(acc1[mt][nt][3]) * acc3[mt][nt][3];
                *(float2*)&g_H[((size_t)e * T_TOK + r1) * HID + col] = o;
            }
        }
    }
}

// ---------------- kernel 3: Y = H @ W2, TF32 mma, scatter-add -----------------
// Block: 128(M) x 128(N) x K-tile 32. 8 warps = 4M x 2N; warp = 32m x 64n.
__global__ __launch_bounds__(256) void gemm_o_kernel(const float* __restrict__ w2,
                                                     float* __restrict__ out) {
    int e = blockIdx.z;
    int cnt = g_count[e];
    int row0 = blockIdx.y * 128;
    if (row0 >= cnt) return;
    int n0 = blockIdx.x * 128;

    __shared__ unsigned As[32][136];
    __shared__ unsigned Bs[32][136];
    __shared__ int s_tok[128];

    int tid = threadIdx.x;
    int warp = tid >> 5, lane = tid & 31;
    int q = lane & 3, g = lane >> 2;
    int wm = warp >> 1, wn = warp & 1;
    int mb = wm * 32;
    int nb = wn * 64;

    if (tid < 128) {
        int r = row0 + tid;
        s_tok[tid] = (r < cnt) ? g_tok[e * T_TOK + r] : 0;
    }
    __syncthreads();

    float acc[2][8][4];
#pragma unroll
    for (int a = 0; a < 2; a++)
#pragma unroll
        for (int b = 0; b < 8; b++)
#pragma unroll
            for (int c = 0; c < 4; c++) acc[a][b][c] = 0.f;

    const float* hb = g_H + (size_t)e * T_TOK * HID;
    const float* w2b = w2 + (size_t)e * HID * DIM + n0;

    for (int kt = 0; kt < HID; kt += 32) {
        // A: 128 x 32 = 1024 float4
#pragma unroll
        for (int i = tid; i < 1024; i += 256) {
            int m = i >> 3, k4 = (i & 7) << 2;
            float4 v = make_float4(0.f, 0.f, 0.f, 0.f);
            if (row0 + m < cnt)
                v = *(const float4*)(hb + (size_t)(row0 + m) * HID + kt + k4);
            As[k4 + 0][m] = f2tf32(v.x);
            As[k4 + 1][m] = f2tf32(v.y);
            As[k4 + 2][m] = f2tf32(v.z);
            As[k4 + 3][m] = f2tf32(v.w);
        }
        // B: 32 x 128 = 1024 float4
#pragma unroll
        for (int i = tid; i < 1024; i += 256) {
            int k = i >> 5, c4 = (i & 31) << 2;
            float4 v = *(const float4*)(w2b + (size_t)(kt + k) * DIM + c4);
            Bs[k][c4 + 0] = f2tf32(v.x); Bs[k][c4 + 1] = f2tf32(v.y);
            Bs[k][c4 + 2] = f2tf32(v.z); Bs[k][c4 + 3] = f2tf32(v.w);
        }
        __syncthreads();

#pragma unroll
        for (int ks = 0; ks < 4; ks++) {
            int k8 = ks * 8;
            unsigned a[2][4];
#pragma unroll
            for (int mt = 0; mt < 2; mt++) {
                int m = mb + mt * 16 + g;
                a[mt][0] = As[k8 + q][m];
                a[mt][1] = As[k8 + q][m + 8];
                a[mt][2] = As[k8 + q + 4][m];
                a[mt][3] = As[k8 + q + 4][m + 8];
            }
#pragma unroll
            for (int nt = 0; nt < 8; nt++) {
                int n = nb + nt * 8 + g;
                unsigned b0 = Bs[k8 + q][n];
                unsigned b1 = Bs[k8 + q + 4][n];
                mma_tf32(acc[0][nt], a[0], b0, b1);
                mma_tf32(acc[1][nt], a[1], b0, b1);
            }
        }
        __syncthreads();
    }

    // epilogue: scatter-add
#pragma unroll
    for (int mt = 0; mt < 2; mt++) {
#pragma unroll
        for (int nt = 0; nt < 8; nt++) {
            int col = n0 + nb + nt * 8 + 2 * q;
            int r0 = row0 + mb + mt * 16 + g;
            int r1 = r0 + 8;
            if (r0 < cnt) {
                float* op = out + (size_t)s_tok[mb + mt * 16 + g] * DIM + col;
                atomicAdd(op + 0, acc[mt][nt][0]);
                atomicAdd(op + 1, acc[mt][nt][1]);
            }
            if (r1 < cnt) {
                float* op = out + (size_t)s_tok[mb + mt * 16 + g + 8] * DIM + col;
                atomicAdd(op + 0, acc[mt][nt][2]);
                atomicAdd(op + 1, acc[mt][nt][3]);
            }
        }
    }
}

// ---------------- launch ------------------------------------------------------
extern "C" void kernel_launch(void* const* d_in, const int* in_sizes, int n_in,
                              void* d_out, int out_size) {
    const float* x  = (const float*)d_in[0];
    const float* rw = (const float*)d_in[1];
    const float* w1 = (const float*)d_in[2];
    const float* w2 = (const float*)d_in[3];
    const float* w3 = (const float*)d_in[4];
    float* out = (float*)d_out;

    int n4 = (T_TOK * DIM) / 4;
    zero_kernel<<<(n4 + 255) / 256, 256>>>(out, n4);
    router_kernel<<<T_TOK / 4, 128>>>(x, rw);

    dim3 gh(HID / 64, T_TOK / 128, NE);    // (32, 16, 8)
    gemm_h_kernel<<<gh, 256>>>(x, w1, w3);

    dim3 go(DIM / 128, T_TOK / 128, NE);   // (8, 16, 8)
    gemm_o_kernel<<<go, 256>>>(w2, out);
}

// round 5
// speedup vs baseline: 4.6376x; 2.4271x over previous
#include <cuda_runtime.h>
#include <cuda_fp16.h>
#include <cstdint>

#define T_TOK 2048
#define DIM   1024
#define HID   2048
#define NE    8

// ---------------- scratch (16B-aligned via uint4) ----------------------------
__device__ int   g_count[NE];
__device__ int   g_tok[NE * T_TOK];
__device__ float g_score[NE * T_TOK];
__device__ int   g_slot[T_TOK * 2];                       // token -> 2 slot ids (e*T_TOK+row)
__device__ uint4 g_w1h[(size_t)NE * DIM * HID / 8];       // fp16 weights
__device__ uint4 g_w2h[(size_t)NE * HID * DIM / 8];
__device__ uint4 g_w3h[(size_t)NE * DIM * HID / 8];
__device__ uint4 g_A [(size_t)NE * T_TOK * DIM / 8];      // dispatched fp16 activations
__device__ uint4 g_H [(size_t)NE * T_TOK * HID / 8];      // fp16 hidden
__device__ float g_Y [(size_t)NE * T_TOK * DIM];          // per-slot fp32 outputs

__device__ __forceinline__ float silu_f(float v) { return v / (1.0f + __expf(-v)); }

__device__ __forceinline__ uint32_t smem_u32(const void* p) {
    uint32_t a;
    asm("{ .reg .u64 t; cvta.to.shared.u64 t, %1; cvt.u32.u64 %0, t; }" : "=r"(a) : "l"(p));
    return a;
}

#define CP16(dst, src) \
    asm volatile("cp.async.cg.shared.global [%0], [%1], 16;" :: "r"(dst), "l"(src) : "memory")
#define CP_COMMIT() asm volatile("cp.async.commit_group;" ::: "memory")
#define CP_WAIT2()  asm volatile("cp.async.wait_group 2;" ::: "memory")

#define LDM_X4(r0, r1, r2, r3, a) \
    asm volatile("ldmatrix.sync.aligned.m8n8.x4.shared.b16 {%0,%1,%2,%3}, [%4];" \
                 : "=r"(r0), "=r"(r1), "=r"(r2), "=r"(r3) : "r"(a))
#define LDM_X4T(r0, r1, r2, r3, a) \
    asm volatile("ldmatrix.sync.aligned.m8n8.x4.trans.shared.b16 {%0,%1,%2,%3}, [%4];" \
                 : "=r"(r0), "=r"(r1), "=r"(r2), "=r"(r3) : "r"(a))

#define MMA16816(c, a, b0, b1) \
    asm volatile("mma.sync.aligned.m16n8k16.row.col.f32.f16.f16.f32 " \
                 "{%0,%1,%2,%3}, {%4,%5,%6,%7}, {%8,%9}, {%0,%1,%2,%3};" \
                 : "+f"((c)[0]), "+f"((c)[1]), "+f"((c)[2]), "+f"((c)[3]) \
                 : "r"((a)[0]), "r"((a)[1]), "r"((a)[2]), "r"((a)[3]), "r"(b0), "r"(b1))

// ---------------- kernel: zero expert counts ---------------------------------
__global__ void zero_cnt_kernel() {
    if (threadIdx.x < NE) g_count[threadIdx.x] = 0;
}

// ---------------- kernel: convert weights fp32 -> fp16 -----------------------
__global__ __launch_bounds__(256) void convert_w_kernel(const float* __restrict__ w1,
                                                        const float* __restrict__ w2,
                                                        const float* __restrict__ w3) {
    const float* src = (blockIdx.z == 0) ? w1 : (blockIdx.z == 1) ? w2 : w3;
    uint4* dst = (blockIdx.z == 0) ? g_w1h : (blockIdx.z == 1) ? g_w2h : g_w3h;
    size_t i8 = (size_t)blockIdx.x * 256 + threadIdx.x;   // index in units of 8 elems
    size_t i = i8 * 8;
    float4 a = *(const float4*)(src + i);
    float4 b = *(const float4*)(src + i + 4);
    __half2 h[4];
    h[0] = __floats2half2_rn(a.x, a.y);
    h[1] = __floats2half2_rn(a.z, a.w);
    h[2] = __floats2half2_rn(b.x, b.y);
    h[3] = __floats2half2_rn(b.z, b.w);
    dst[i8] = *(uint4*)h;
}

// ---------------- kernel: router ---------------------------------------------
__global__ void router_kernel(const float* __restrict__ x,
                              const float* __restrict__ rw) {
    int warp = threadIdx.x >> 5;
    int lane = threadIdx.x & 31;
    int tok = blockIdx.x * 4 + warp;
    if (tok >= T_TOK) return;

    const float* xr = x + (size_t)tok * DIM;
    float xv[32];
#pragma unroll
    for (int j = 0; j < 32; j++) xv[j] = xr[lane + 32 * j];

    float logit[NE];
#pragma unroll
    for (int e = 0; e < NE; e++) {
        float p = 0.f;
#pragma unroll
        for (int j = 0; j < 32; j++) p += xv[j] * rw[(lane + 32 * j) * NE + e];
#pragma unroll
        for (int o = 16; o > 0; o >>= 1) p += __shfl_xor_sync(0xffffffffu, p, o);
        logit[e] = p;
    }

    if (lane == 0) {
        float mx = logit[0];
#pragma unroll
        for (int e = 1; e < NE; e++) mx = fmaxf(mx, logit[e]);
        float pr[NE]; float sum = 0.f;
#pragma unroll
        for (int e = 0; e < NE; e++) { pr[e] = __expf(logit[e] - mx); sum += pr[e]; }
        float inv = 1.f / sum;
#pragma unroll
        for (int e = 0; e < NE; e++) pr[e] *= inv;

        int i1 = 0;
#pragma unroll
        for (int e = 1; e < NE; e++) if (pr[e] > pr[i1]) i1 = e;
        int i2 = -1;
#pragma unroll
        for (int e = 0; e < NE; e++) {
            if (e == i1) continue;
            if (i2 < 0 || pr[e] > pr[i2]) i2 = e;
        }
        int s1 = atomicAdd(&g_count[i1], 1);
        g_tok[i1 * T_TOK + s1] = tok;  g_score[i1 * T_TOK + s1] = pr[i1];
        g_slot[tok * 2] = i1 * T_TOK + s1;
        int s2 = atomicAdd(&g_count[i2], 1);
        g_tok[i2 * T_TOK + s2] = tok;  g_score[i2 * T_TOK + s2] = pr[i2];
        g_slot[tok * 2 + 1] = i2 * T_TOK + s2;
    }
}

// ---------------- kernel: dispatch (build g_A = x[tok]*score, fp16) ----------
__global__ __launch_bounds__(128) void dispatch_kernel(const float* __restrict__ x) {
    int e = blockIdx.x;
    int row = blockIdx.y;
    if (row >= g_count[e]) return;
    int tok = g_tok[e * T_TOK + row];
    float sc = g_score[e * T_TOK + row];
    const float* xr = x + (size_t)tok * DIM + threadIdx.x * 8;
    float4 a = *(const float4*)(xr);
    float4 b = *(const float4*)(xr + 4);
    __half2 h[4];
    h[0] = __floats2half2_rn(a.x * sc, a.y * sc);
    h[1] = __floats2half2_rn(a.z * sc, a.w * sc);
    h[2] = __floats2half2_rn(b.x * sc, b.y * sc);
    h[3] = __floats2half2_rn(b.z * sc, b.w * sc);
    g_A[((size_t)e * T_TOK + row) * (DIM / 8) + threadIdx.x] = *(uint4*)h;
}

// ---------------- GEMM H: H = silu(A@W1) * (A@W3) ----------------------------
// CTA 128M x (64 w1-cols + 64 w3-cols), 4 warps, warp = 32M x 128N.
// 4-stage cp.async pipeline, k-chunk 32.
#define STG_H 19456   // A: 128*80 = 10240 | B1: 32*144 = 4608 | B3: 4608
#define SMEM_H (4 * STG_H)

__global__ __launch_bounds__(128) void gemm_h_fp16() {
    extern __shared__ char smem[];
    int e = blockIdx.z;
    int cnt = g_count[e];
    int row0 = blockIdx.y * 128;
    if (row0 >= cnt) return;
    int n0 = blockIdx.x * 64;

    int tid = threadIdx.x, warp = tid >> 5, lane = tid & 31;
    uint32_t sb = smem_u32(smem);
    const __half* gA  = (const __half*)g_A + (size_t)e * T_TOK * DIM;
    const __half* w1h = (const __half*)g_w1h + (size_t)e * DIM * HID + n0;
    const __half* w3h = (const __half*)g_w3h + (size_t)e * DIM * HID + n0;

    auto issue = [&](int c) {
        if (c < DIM / 32) {
            int kt = c * 32;
            uint32_t st = sb + (c & 3) * STG_H;
#pragma unroll
            for (int it = 0; it < 4; it++) {
                int gi = tid + it * 128;
                int row = gi >> 2, ks = gi & 3;
                CP16(st + row * 80 + ks * 16,
                     gA + (size_t)(row0 + row) * DIM + kt + ks * 8);
            }
#pragma unroll
            for (int it = 0; it < 4; it++) {
                int gi = tid + it * 128;
                int slab = gi >> 8, r = gi & 255, kr = r >> 3, ns = r & 7;
                const __half* src = (slab ? w3h : w1h) + (size_t)(kt + kr) * HID + ns * 8;
                CP16(st + 10240 + slab * 4608 + kr * 144 + ns * 16, src);
            }
        }
        CP_COMMIT();
    };

    issue(0); issue(1); issue(2);

    float acc1[2][8][4], acc3[2][8][4];
#pragma unroll
    for (int a = 0; a < 2; a++)
#pragma unroll
        for (int b = 0; b < 8; b++)
#pragma unroll
            for (int c = 0; c < 4; c++) { acc1[a][b][c] = 0.f; acc3[a][b][c] = 0.f; }

    int mb = warp * 32;

#pragma unroll 1
    for (int c = 0; c < DIM / 32; c++) {
        CP_WAIT2();
        __syncthreads();
        uint32_t st = sb + (c & 3) * STG_H;
        uint32_t SA = st, SB1 = st + 10240, SB3 = st + 14848;

#pragma unroll
        for (int ks = 0; ks < 2; ks++) {
            int k0 = ks * 16;
            uint32_t a[2][4];
#pragma unroll
            for (int mt = 0; mt < 2; mt++) {
                uint32_t addr = SA + (mb + mt * 16 + (lane & 15)) * 80
                                   + (k0 + (lane >> 4) * 8) * 2;
                LDM_X4(a[mt][0], a[mt][1], a[mt][2], a[mt][3], addr);
            }
            uint32_t koff = (k0 + ((lane >> 3) & 1) * 8 + (lane & 7));
            uint32_t ncol = (lane >> 4) * 8;
#pragma unroll
            for (int ng = 0; ng < 4; ng++) {
                uint32_t b0, b1, b2, b3;
                LDM_X4T(b0, b1, b2, b3, SB1 + koff * 144 + (ng * 16 + ncol) * 2);
#pragma unroll
                for (int mt = 0; mt < 2; mt++) {
                    MMA16816(acc1[mt][ng * 2 + 0], a[mt], b0, b1);
                    MMA16816(acc1[mt][ng * 2 + 1], a[mt], b2, b3);
                }
                LDM_X4T(b0, b1, b2, b3, SB3 + koff * 144 + (ng * 16 + ncol) * 2);
#pragma unroll
                for (int mt = 0; mt < 2; mt++) {
                    MMA16816(acc3[mt][ng * 2 + 0], a[mt], b0, b1);
                    MMA16816(acc3[mt][ng * 2 + 1], a[mt], b2, b3);
                }
            }
        }
        issue(c + 3);
    }

    // epilogue: h = silu(c1)*c3 -> g_H (fp16)
    __half* gH = (__half*)g_H;
#pragma unroll
    for (int mt = 0; mt < 2; mt++) {
        int rA = row0 + mb + mt * 16 + (lane >> 2);
        int rB = rA + 8;
#pragma unroll
        for (int j = 0; j < 8; j++) {
            int col = n0 + j * 8 + (lane & 3) * 2;
            if (rA < cnt) {
                float h0 = silu_f(acc1[mt][j][0]) * acc3[mt][j][0];
                float h1 = silu_f(acc1[mt][j][1]) * acc3[mt][j][1];
                *(half2*)(gH + ((size_t)e * T_TOK + rA) * HID + col) = __floats2half2_rn(h0, h1);
            }
            if (rB < cnt) {
                float h0 = silu_f(acc1[mt][j][2]) * acc3[mt][j][2];
                float h1 = silu_f(acc1[mt][j][3]) * acc3[mt][j][3];
                *(half2*)(gH + ((size_t)e * T_TOK + rB) * HID + col) = __floats2half2_rn(h0, h1);
            }
        }
    }
}

// ---------------- GEMM O: Y = H @ W2 -> g_Y (per-slot, no atomics) -----------
// CTA 128M x 128N, 4 warps, warp = 32M x 128N, k-chunk 32, 4-stage cp.async.
#define STG_O 18944   // A: 10240 | B: 32*272 = 8704
#define SMEM_O (4 * STG_O)

__global__ __launch_bounds__(128) void gemm_o_fp16() {
    extern __shared__ char smem[];
    int e = blockIdx.z;
    int cnt = g_count[e];
    int row0 = blockIdx.y * 128;
    if (row0 >= cnt) return;
    int n0 = blockIdx.x * 128;

    int tid = threadIdx.x, warp = tid >> 5, lane = tid & 31;
    uint32_t sb = smem_u32(smem);
    const __half* gH  = (const __half*)g_H + (size_t)e * T_TOK * HID;
    const __half* w2h = (const __half*)g_w2h + (size_t)e * HID * DIM + n0;

    auto issue = [&](int c) {
        if (c < HID / 32) {
            int kt = c * 32;
            uint32_t st = sb + (c & 3) * STG_O;
#pragma unroll
            for (int it = 0; it < 4; it++) {
                int gi = tid + it * 128;
                int row = gi >> 2, ks = gi & 3;
                CP16(st + row * 80 + ks * 16,
                     gH + (size_t)(row0 + row) * HID + kt + ks * 8);
            }
#pragma unroll
            for (int it = 0; it < 4; it++) {
                int gi = tid + it * 128;
                int kr = gi >> 4, ns = gi & 15;
                CP16(st + 10240 + kr * 272 + ns * 16,
                     w2h + (size_t)(kt + kr) * DIM + ns * 8);
            }
        }
        CP_COMMIT();
    };

    issue(0); issue(1); issue(2);

    float acc[2][16][4];
#pragma unroll
    for (int a = 0; a < 2; a++)
#pragma unroll
        for (int b = 0; b < 16; b++)
#pragma unroll
            for (int c = 0; c < 4; c++) acc[a][b][c] = 0.f;

    int mb = warp * 32;

#pragma unroll 1
    for (int c = 0; c < HID / 32; c++) {
        CP_WAIT2();
        __syncthreads();
        uint32_t st = sb + (c & 3) * STG_O;
        uint32_t SA = st, SB = st + 10240;

#pragma unroll
        for (int ks = 0; ks < 2; ks++) {
            int k0 = ks * 16;
            uint32_t a[2][4];
#pragma unroll
            for (int mt = 0; mt < 2; mt++) {
                uint32_t addr = SA + (mb + mt * 16 + (lane & 15)) * 80
                                   + (k0 + (lane >> 4) * 8) * 2;
                LDM_X4(a[mt][0], a[mt][1], a[mt][2], a[mt][3], addr);
            }
            uint32_t koff = (k0 + ((lane >> 3) & 1) * 8 + (lane & 7));
            uint32_t ncol = (lane >> 4) * 8;
#pragma unroll
            for (int ng = 0; ng < 8; ng++) {
                uint32_t b0, b1, b2, b3;
                LDM_X4T(b0, b1, b2, b3, SB + koff * 272 + (ng * 16 + ncol) * 2);
#pragma unroll
                for (int mt = 0; mt < 2; mt++) {
                    MMA16816(acc[mt][ng * 2 + 0], a[mt], b0, b1);
                    MMA16816(acc[mt][ng * 2 + 1], a[mt], b2, b3);
                }
            }
        }
        issue(c + 3);
    }

    // epilogue: plain float2 stores into per-slot buffer
#pragma unroll
    for (int mt = 0; mt < 2; mt++) {
        int rA = row0 + mb + mt * 16 + (lane >> 2);
        int rB = rA + 8;
#pragma unroll
        for (int j = 0; j < 16; j++) {
            int col = n0 + j * 8 + (lane & 3) * 2;
            if (rA < cnt) {
                float2 v = make_float2(acc[mt][j][0], acc[mt][j][1]);
                *(float2*)(g_Y + ((size_t)e * T_TOK + rA) * DIM + col) = v;
            }
            if (rB < cnt) {
                float2 v = make_float2(acc[mt][j][2], acc[mt][j][3]);
                *(float2*)(g_Y + ((size_t)e * T_TOK + rB) * DIM + col) = v;
            }
        }
    }
}

// ---------------- kernel: combine (sum 2 slots per token) --------------------
__global__ __launch_bounds__(256) void combine_kernel(float* __restrict__ out) {
    int idx = blockIdx.x * 256 + threadIdx.x;            // float4 index
    int t = idx >> 8;                                    // DIM/4 = 256 per token
    int c4 = idx & 255;
    int s0 = g_slot[t * 2], s1 = g_slot[t * 2 + 1];
    const float4* y = (const float4*)g_Y;
    float4 a = y[(size_t)s0 * 256 + c4];
    float4 b = y[(size_t)s1 * 256 + c4];
    ((float4*)out)[idx] = make_float4(a.x + b.x, a.y + b.y, a.z + b.z, a.w + b.w);
}

// ---------------- launch ------------------------------------------------------
extern "C" void kernel_launch(void* const* d_in, const int* in_sizes, int n_in,
                              void* d_out, int out_size) {
    const float* x  = (const float*)d_in[0];
    const float* rw = (const float*)d_in[1];
    const float* w1 = (const float*)d_in[2];
    const float* w2 = (const float*)d_in[3];
    const float* w3 = (const float*)d_in[4];
    float* out = (float*)d_out;

    cudaFuncSetAttribute(gemm_h_fp16, cudaFuncAttributeMaxDynamicSharedMemorySize, SMEM_H);
    cudaFuncSetAttribute(gemm_o_fp16, cudaFuncAttributeMaxDynamicSharedMemorySize, SMEM_O);

    zero_cnt_kernel<<<1, 32>>>();
    convert_w_kernel<<<dim3(NE * DIM * HID / 8 / 256, 1, 3), 256>>>(w1, w2, w3);
    router_kernel<<<T_TOK / 4, 128>>>(x, rw);
    dispatch_kernel<<<dim3(NE, T_TOK), 128>>>(x);

    dim3 gh(HID / 64, T_TOK / 128, NE);    // (32, 16, 8)
    gemm_h_fp16<<<gh, 128, SMEM_H>>>();

    dim3 go(DIM / 128, T_TOK / 128, NE);   // (8, 16, 8)
    gemm_o_fp16<<<go, 128, SMEM_O>>>();

    combine_kernel<<<T_TOK * DIM / 4 / 256, 256>>>(out);
}